// round 5
// baseline (speedup 1.0000x reference)
#include <cuda_runtime.h>
#include <cuda_bf16.h>
#include <math.h>

// DescriptorBuilder: periodic minimum-image descriptors (O(N^2) factorized).
// Radial:  q_r[i,k] = sum_j fc(r_ij) * r_ij^k, k=0..8
// Angular: q_ang[i,n,0] = S_n^2, S_n = sum_j fc r^n
//          q_ang[i,n,1] = |V_n|^2, V_n = sum_j fc r^(n-1) dr
//          q_ang[i,n,2] = 0.5*(3*||M_n||_F^2 - S_n^2), M_n = sum_j fc r^(n-2) dr(x)dr
//
// One WARP per atom, 2 atoms per 64-thread block, 96 blocks = one wave.
// NO shared memory, NO __syncthreads: direct global loads (L2-resident across
// graph replays; 6 independent iterations batch ~18 LDGs into one round trip),
// full in-warp butterfly so every lane holds all 36 sums, lanes 0..17 each
// compute and store one output element.

#define BLOCK 64
#define RCUT 6.0f

__global__ void __launch_bounds__(BLOCK)
desc_kernel(const float* __restrict__ R,
            const float* __restrict__ box,
            float* __restrict__ out, int N)
{
    const int t    = threadIdx.x;
    const int lane = t & 31;
    const int warp = t >> 5;                // 0/1
    const int i    = blockIdx.x * 2 + warp; // atom this warp owns
    if (i >= N) return;

    // Box + inverse in registers (redundant per thread, cheap).
    float b[9];
#pragma unroll
    for (int k = 0; k < 9; k++) b[k] = __ldg(box + k);

    const bool diag = (b[1] == 0.f && b[2] == 0.f && b[3] == 0.f &&
                       b[5] == 0.f && b[6] == 0.f && b[7] == 0.f);

    const float det =
        b[0] * (b[4] * b[8] - b[5] * b[7]) -
        b[1] * (b[3] * b[8] - b[5] * b[6]) +
        b[2] * (b[3] * b[7] - b[4] * b[6]);
    const float idet = 1.0f / det;
    float inv[9];
    inv[0] = (b[4] * b[8] - b[5] * b[7]) * idet;
    inv[1] = (b[2] * b[7] - b[1] * b[8]) * idet;
    inv[2] = (b[1] * b[5] - b[2] * b[4]) * idet;
    inv[3] = (b[5] * b[6] - b[3] * b[8]) * idet;
    inv[4] = (b[0] * b[8] - b[2] * b[6]) * idet;
    inv[5] = (b[2] * b[3] - b[0] * b[5]) * idet;
    inv[6] = (b[3] * b[7] - b[4] * b[6]) * idet;
    inv[7] = (b[1] * b[6] - b[0] * b[7]) * idet;
    inv[8] = (b[0] * b[4] - b[1] * b[3]) * idet;

    const float PI_OVER_RC = 3.14159265358979323846f / RCUT;

    // Accumulators: [0..8] radial (S_n = acc[n]); [9..17] V_n; [18..35] M_n.
    float acc[36];
#pragma unroll
    for (int k = 0; k < 36; k++) acc[k] = 0.0f;

    const float rix = __ldg(R + 3 * i + 0);
    const float riy = __ldg(R + 3 * i + 1);
    const float riz = __ldg(R + 3 * i + 2);

#pragma unroll 6
    for (int j = lane; j < N; j += 32) {
        if (j == i) continue;
        // Cartesian displacement, then minimum image via fractional round.
        float cx = rix - __ldg(R + 3 * j + 0);
        float cy = riy - __ldg(R + 3 * j + 1);
        float cz = riz - __ldg(R + 3 * j + 2);
        float dx, dy, dz;
        if (diag) {
            dx = cx - b[0] * rintf(inv[0] * cx);
            dy = cy - b[4] * rintf(inv[4] * cy);
            dz = cz - b[8] * rintf(inv[8] * cz);
        } else {
            float f0 = rintf(inv[0] * cx + inv[1] * cy + inv[2] * cz);
            float f1 = rintf(inv[3] * cx + inv[4] * cy + inv[5] * cz);
            float f2 = rintf(inv[6] * cx + inv[7] * cy + inv[8] * cz);
            dx = cx - (b[0] * f0 + b[1] * f1 + b[2] * f2);
            dy = cy - (b[3] * f0 + b[4] * f1 + b[5] * f2);
            dz = cz - (b[6] * f0 + b[7] * f1 + b[8] * f2);
        }
        float r2 = dx * dx + dy * dy + dz * dz;
        float invr = rsqrtf(r2);
        float r = r2 * invr;
        if (r >= RCUT) continue;   // fc exactly 0 there

        float fc = 0.5f * __cosf(r * PI_OVER_RC) + 0.5f;

        // Radial moments fc * r^k, k = 0..8 (log-depth powers)
        float rr2 = r * r;
        float rr3 = rr2 * r;
        float rr4 = rr2 * rr2;
        float fcr4 = fc * rr4;
        acc[0] += fc;
        acc[1] += fc * r;
        acc[2] += fc * rr2;
        acc[3] += fc * rr3;
        acc[4] += fcr4;
        acc[5] += fcr4 * r;
        acc[6] += fcr4 * rr2;
        acc[7] += fcr4 * rr3;
        acc[8] += fcr4 * rr4;

        // Angular weights: wv_n = fc r^(n-1), wm_n = fc r^(n-2)
        float wv0 = fc * invr;
        float wv2 = fc * r;
        float wm0 = wv0 * invr;
        float xx = dx * dx, xy = dx * dy, xz = dx * dz;
        float yy = dy * dy, yz = dy * dz, zz = dz * dz;

        acc[9]  += wv0 * dx;  acc[10] += wv0 * dy;  acc[11] += wv0 * dz;
        acc[12] += fc  * dx;  acc[13] += fc  * dy;  acc[14] += fc  * dz;
        acc[15] += wv2 * dx;  acc[16] += wv2 * dy;  acc[17] += wv2 * dz;

        acc[18] += wm0 * xx;  acc[19] += wm0 * xy;  acc[20] += wm0 * xz;
        acc[21] += wm0 * yy;  acc[22] += wm0 * yz;  acc[23] += wm0 * zz;
        acc[24] += wv0 * xx;  acc[25] += wv0 * xy;  acc[26] += wv0 * xz;
        acc[27] += wv0 * yy;  acc[28] += wv0 * yz;  acc[29] += wv0 * zz;
        acc[30] += fc  * xx;  acc[31] += fc  * xy;  acc[32] += fc  * xz;
        acc[33] += fc  * yy;  acc[34] += fc  * yz;  acc[35] += fc  * zz;
    }

    // Full warp butterfly: afterwards EVERY lane holds all 36 sums.
#pragma unroll
    for (int o = 16; o > 0; o >>= 1) {
#pragma unroll
        for (int k = 0; k < 36; k++)
            acc[k] += __shfl_xor_sync(0xffffffffu, acc[k], o);
    }

    // Distributed epilogue: lanes 0..17 each produce one output element.
    if (lane < 18) {
        float val;
        if (lane < 9) {
            val = acc[lane];
        } else {
            int idx = lane - 9;
            int n = idx / 3;
            int l = idx - 3 * n;
            float s = acc[n];
            if (l == 0) {
                val = s * s;
            } else if (l == 1) {
                float vx = acc[9 + 3 * n], vy = acc[10 + 3 * n], vz = acc[11 + 3 * n];
                val = vx * vx + vy * vy + vz * vz;
            } else {
                float m0 = acc[18 + 6 * n], m1 = acc[19 + 6 * n], m2 = acc[20 + 6 * n];
                float m3 = acc[21 + 6 * n], m4 = acc[22 + 6 * n], m5 = acc[23 + 6 * n];
                float frob = m0 * m0 + m3 * m3 + m5 * m5 +
                             2.0f * (m1 * m1 + m2 * m2 + m4 * m4);
                val = 0.5f * (3.0f * frob - s * s);
            }
        }
        out[(size_t)i * 18 + lane] = val;
    }
}

extern "C" void kernel_launch(void* const* d_in, const int* in_sizes, int n_in,
                              void* d_out, int out_size) {
    const float* R   = (const float*)d_in[0];   // [N,3] fp32
    // d_in[1] = Z (int32), unused by the reference math
    const float* box = (const float*)d_in[2];   // [3,3] fp32
    float* out = (float*)d_out;                 // [N,18] fp32
    const int N = in_sizes[0] / 3;
    const int blocks = (N + 1) / 2;             // one warp per atom
    desc_kernel<<<blocks, BLOCK>>>(R, box, out, N);
}

// round 6
// speedup vs baseline: 1.2917x; 1.2917x over previous
#include <cuda_runtime.h>
#include <cuda_bf16.h>
#include <math.h>

// DescriptorBuilder: periodic minimum-image descriptors (O(N^2) factorized).
// Radial:  q_r[i,k] = sum_j fc(r_ij) * r_ij^k, k=0..8
// Angular: q_ang[i,n,0] = S_n^2, S_n = sum_j fc r^n
//          q_ang[i,n,1] = |V_n|^2, V_n = sum_j fc r^(n-1) dr
//          q_ang[i,n,2] = 0.5*(3*||M_n||_F^2 - S_n^2), M_n = sum_j fc r^(n-2) dr(x)dr
//
// R3-winning structure: 128 threads/block, 2 warps per atom (split j-range),
// 2 atoms per block, 96 blocks = one wave, smem-staged coordinates.
// Improvements: raw-Cartesian staging (pure copy), split-butterfly reduction
// (71 shuffles instead of 180) ending in a deterministic smem scatter,
// 18-lane distributed epilogue reading the two partial buffers.

#define BLOCK 128
#define MAXN 512
#define RCUT 6.0f

__global__ void __launch_bounds__(BLOCK)
desc_kernel(const float* __restrict__ R,
            const float* __restrict__ box,
            float* __restrict__ out, int N)
{
    __shared__ float s0[MAXN], s1[MAXN], s2[MAXN];   // raw Cartesian coords
    __shared__ float sred[2][2][36];                 // [atom slot][sub][36]

    const int t    = threadIdx.x;
    const int lane = t & 31;
    const int warp = t >> 5;        // 0..3
    const int a    = warp >> 1;     // atom slot (0/1)
    const int sub  = warp & 1;      // j-range half
    const int i    = blockIdx.x * 2 + a;
    const bool valid = (i < N);

    // Box + inverse in registers (redundant per thread, cheap).
    float b[9];
#pragma unroll
    for (int k = 0; k < 9; k++) b[k] = __ldg(box + k);

    const bool diag = (b[1] == 0.f && b[2] == 0.f && b[3] == 0.f &&
                       b[5] == 0.f && b[6] == 0.f && b[7] == 0.f);

    const float det =
        b[0] * (b[4] * b[8] - b[5] * b[7]) -
        b[1] * (b[3] * b[8] - b[5] * b[6]) +
        b[2] * (b[3] * b[7] - b[4] * b[6]);
    const float idet = 1.0f / det;
    float inv[9];
    inv[0] = (b[4] * b[8] - b[5] * b[7]) * idet;
    inv[1] = (b[2] * b[7] - b[1] * b[8]) * idet;
    inv[2] = (b[1] * b[5] - b[2] * b[4]) * idet;
    inv[3] = (b[5] * b[6] - b[3] * b[8]) * idet;
    inv[4] = (b[0] * b[8] - b[2] * b[6]) * idet;
    inv[5] = (b[2] * b[3] - b[0] * b[5]) * idet;
    inv[6] = (b[3] * b[7] - b[4] * b[6]) * idet;
    inv[7] = (b[1] * b[6] - b[0] * b[7]) * idet;
    inv[8] = (b[0] * b[4] - b[1] * b[3]) * idet;

    // Stage raw coordinates (pure copy; 3 separate arrays = conflict-free LDS).
    for (int j = t; j < N; j += BLOCK) {
        s0[j] = __ldg(R + 3 * j + 0);
        s1[j] = __ldg(R + 3 * j + 1);
        s2[j] = __ldg(R + 3 * j + 2);
    }
    __syncthreads();

    const float PI_OVER_RC = 3.14159265358979323846f / RCUT;

    // Accumulators: [0..8] radial (S_n = acc[n]); [9..17] V_n; [18..35] M_n.
    float acc[36];
#pragma unroll
    for (int k = 0; k < 36; k++) acc[k] = 0.0f;

    if (valid) {
        const float rix = s0[i], riy = s1[i], riz = s2[i];

        for (int j = lane + 32 * sub; j < N; j += 64) {
            if (j == i) continue;
            float cx = rix - s0[j];
            float cy = riy - s1[j];
            float cz = riz - s2[j];
            float dx, dy, dz;
            if (diag) {
                dx = cx - b[0] * rintf(inv[0] * cx);
                dy = cy - b[4] * rintf(inv[4] * cy);
                dz = cz - b[8] * rintf(inv[8] * cz);
            } else {
                float f0 = rintf(inv[0] * cx + inv[1] * cy + inv[2] * cz);
                float f1 = rintf(inv[3] * cx + inv[4] * cy + inv[5] * cz);
                float f2 = rintf(inv[6] * cx + inv[7] * cy + inv[8] * cz);
                dx = cx - (b[0] * f0 + b[1] * f1 + b[2] * f2);
                dy = cy - (b[3] * f0 + b[4] * f1 + b[5] * f2);
                dz = cz - (b[6] * f0 + b[7] * f1 + b[8] * f2);
            }
            float r2 = dx * dx + dy * dy + dz * dz;
            float invr = rsqrtf(r2);
            float r = r2 * invr;
            if (r >= RCUT) continue;   // fc exactly 0 there

            float fc = 0.5f * __cosf(r * PI_OVER_RC) + 0.5f;

            // Radial moments fc * r^k, k = 0..8 (log-depth powers)
            float rr2 = r * r;
            float rr3 = rr2 * r;
            float rr4 = rr2 * rr2;
            float fcr4 = fc * rr4;
            acc[0] += fc;
            acc[1] += fc * r;
            acc[2] += fc * rr2;
            acc[3] += fc * rr3;
            acc[4] += fcr4;
            acc[5] += fcr4 * r;
            acc[6] += fcr4 * rr2;
            acc[7] += fcr4 * rr3;
            acc[8] += fcr4 * rr4;

            // Angular weights: wv_n = fc r^(n-1), wm_n = fc r^(n-2)
            float wv0 = fc * invr;
            float wv2 = fc * r;
            float wm0 = wv0 * invr;
            float xx = dx * dx, xy = dx * dy, xz = dx * dz;
            float yy = dy * dy, yz = dy * dz, zz = dz * dz;

            acc[9]  += wv0 * dx;  acc[10] += wv0 * dy;  acc[11] += wv0 * dz;
            acc[12] += fc  * dx;  acc[13] += fc  * dy;  acc[14] += fc  * dz;
            acc[15] += wv2 * dx;  acc[16] += wv2 * dy;  acc[17] += wv2 * dz;

            acc[18] += wm0 * xx;  acc[19] += wm0 * xy;  acc[20] += wm0 * xz;
            acc[21] += wm0 * yy;  acc[22] += wm0 * yz;  acc[23] += wm0 * zz;
            acc[24] += wv0 * xx;  acc[25] += wv0 * xy;  acc[26] += wv0 * xz;
            acc[27] += wv0 * yy;  acc[28] += wv0 * yz;  acc[29] += wv0 * zz;
            acc[30] += fc  * xx;  acc[31] += fc  * xy;  acc[32] += fc  * xz;
            acc[33] += fc  * yy;  acc[34] += fc  * yz;  acc[35] += fc  * zz;
        }

        // ---- Split-butterfly warp reduction: 36 -> 18 -> 9 -> 5 -> 3 -> 2 ----
        float v18[18];
        {
            const bool up = (lane & 16) != 0;
#pragma unroll
            for (int k = 0; k < 18; k++) {
                float lo = acc[k]      + __shfl_xor_sync(0xffffffffu, acc[k], 16);
                float hi = acc[18 + k] + __shfl_xor_sync(0xffffffffu, acc[18 + k], 16);
                v18[k] = up ? hi : lo;
            }
        }
        float v9[9];
        {
            const bool up = (lane & 8) != 0;
#pragma unroll
            for (int k = 0; k < 9; k++) {
                float lo = v18[k]     + __shfl_xor_sync(0xffffffffu, v18[k], 8);
                float hi = v18[9 + k] + __shfl_xor_sync(0xffffffffu, v18[9 + k], 8);
                v9[k] = up ? hi : lo;
            }
        }
        float v5[5];
        {
            const bool up = (lane & 4) != 0;
#pragma unroll
            for (int k = 0; k < 5; k++) {
                float lo = v9[k] + __shfl_xor_sync(0xffffffffu, v9[k], 4);
                float hi = 0.0f;
                if (k < 4)
                    hi = v9[5 + k] + __shfl_xor_sync(0xffffffffu, v9[5 + k], 4);
                v5[k] = up ? hi : lo;   // upper group: only 4 valid
            }
        }
        float v3[3];
        {
            const bool up = (lane & 2) != 0;
#pragma unroll
            for (int k = 0; k < 3; k++) {
                float lo = v5[k] + __shfl_xor_sync(0xffffffffu, v5[k], 2);
                float hi = 0.0f;
                if (k < 2)
                    hi = v5[3 + k] + __shfl_xor_sync(0xffffffffu, v5[3 + k], 2);
                v3[k] = up ? hi : lo;
            }
        }
        float v2[2];
        {
            const bool up = (lane & 1) != 0;
#pragma unroll
            for (int k = 0; k < 2; k++) {
                float lo = v3[k] + __shfl_xor_sync(0xffffffffu, v3[k], 1);
                float hi = 0.0f;
                if (k < 1)
                    hi = v3[2] + __shfl_xor_sync(0xffffffffu, v3[2], 1);
                v2[k] = up ? hi : lo;
            }
        }

        // Deterministic scatter of fully-reduced values into this warp's slot.
        const int b4 = (lane >> 4) & 1, b3 = (lane >> 3) & 1;
        const int b2 = (lane >> 2) & 1, b1 = (lane >> 1) & 1, b0 = lane & 1;
        const int gsize = b2 ? 4 : 5;
        const int off0  = b1 * 3 + b0 * 2;
        const int base  = b4 * 18 + b3 * 9 + b2 * 5;
        if (off0 < gsize)                sred[a][sub][base + off0]     = v2[0];
        if (b0 == 0 && off0 + 1 < gsize) sred[a][sub][base + off0 + 1] = v2[1];
    }
    __syncthreads();

    // Epilogue: 18 lanes of the sub==0 warp combine the two halves + write.
    if (valid && sub == 0 && lane < 18) {
        const float* p0 = sred[a][0];
        const float* p1 = sred[a][1];
#define TOT(k) (p0[k] + p1[k])

        float val;
        if (lane < 9) {
            val = TOT(lane);
        } else {
            int idx = lane - 9;
            int n = idx / 3;
            int l = idx - 3 * n;
            float s = TOT(n);
            if (l == 0) {
                val = s * s;
            } else if (l == 1) {
                float vx = TOT(9 + 3 * n), vy = TOT(10 + 3 * n), vz = TOT(11 + 3 * n);
                val = vx * vx + vy * vy + vz * vz;
            } else {
                float m0 = TOT(18 + 6 * n), m1 = TOT(19 + 6 * n), m2 = TOT(20 + 6 * n);
                float m3 = TOT(21 + 6 * n), m4 = TOT(22 + 6 * n), m5 = TOT(23 + 6 * n);
                float frob = m0 * m0 + m3 * m3 + m5 * m5 +
                             2.0f * (m1 * m1 + m2 * m2 + m4 * m4);
                val = 0.5f * (3.0f * frob - s * s);
            }
        }
        out[(size_t)i * 18 + lane] = val;
#undef TOT
    }
}

extern "C" void kernel_launch(void* const* d_in, const int* in_sizes, int n_in,
                              void* d_out, int out_size) {
    const float* R   = (const float*)d_in[0];   // [N,3] fp32
    // d_in[1] = Z (int32), unused by the reference math
    const float* box = (const float*)d_in[2];   // [3,3] fp32
    float* out = (float*)d_out;                 // [N,18] fp32
    const int N = in_sizes[0] / 3;
    const int blocks = (N + 1) / 2;             // 2 atoms per block
    desc_kernel<<<blocks, BLOCK>>>(R, box, out, N);
}

// round 7
// speedup vs baseline: 1.3037x; 1.0093x over previous
#include <cuda_runtime.h>
#include <cuda_bf16.h>
#include <math.h>

// DescriptorBuilder: periodic minimum-image descriptors (O(N^2) factorized).
// Radial:  q_r[i,k] = sum_j fc(r_ij) * r_ij^k, k=0..8
// Angular: q_ang[i,n,0] = S_n^2, S_n = sum_j fc r^n
//          q_ang[i,n,1] = |V_n|^2, V_n = sum_j fc r^(n-1) dr
//          q_ang[i,n,2] = 0.5*(3*||M_n||_F^2 - S_n^2), M_n = sum_j fc r^(n-2) dr(x)dr
//
// 128 threads/block, 2 warps per atom (split j-range), 2 atoms/block,
// 96 blocks = one wave. float4 vectorized smem staging, diagonal-box fast
// path (no 3x3 inverse), split-butterfly warp reduction (71 shuffles),
// atom-pair-scoped named barrier before the 18-lane distributed epilogue.

#define BLOCK 128
#define MAXN 512
#define RCUT 6.0f

__global__ void __launch_bounds__(BLOCK)
desc_kernel(const float* __restrict__ R,
            const float* __restrict__ box,
            float* __restrict__ out, int N)
{
    __shared__ float sR[MAXN * 3];      // flat Cartesian coords (float4-staged)
    __shared__ float sred[2][2][36];    // [atom slot][sub-warp][36 partials]

    const int t    = threadIdx.x;
    const int lane = t & 31;
    const int warp = t >> 5;        // 0..3
    const int a    = warp >> 1;     // atom slot (0/1)
    const int sub  = warp & 1;      // j-range half
    const int i    = blockIdx.x * 2 + a;
    const bool valid = (i < N);

    // ---- Vectorized staging: 3N floats as float4 chunks ----
    {
        const int nflt = 3 * N;
        const int nvec = nflt >> 2;
        const float4* R4 = reinterpret_cast<const float4*>(R);
        float4* s4 = reinterpret_cast<float4*>(sR);
        for (int v = t; v < nvec; v += BLOCK) s4[v] = __ldg(R4 + v);
        for (int v = (nvec << 2) + t; v < nflt; v += BLOCK) sR[v] = __ldg(R + v);
    }

    // Box in registers; diagonal fast path avoids the 3x3 inverse.
    float b[9];
#pragma unroll
    for (int k = 0; k < 9; k++) b[k] = __ldg(box + k);

    const bool diag = (b[1] == 0.f && b[2] == 0.f && b[3] == 0.f &&
                       b[5] == 0.f && b[6] == 0.f && b[7] == 0.f);

    float inv[9];
    if (diag) {
        inv[0] = 1.0f / b[0];
        inv[4] = 1.0f / b[4];
        inv[8] = 1.0f / b[8];
    } else {
        const float det =
            b[0] * (b[4] * b[8] - b[5] * b[7]) -
            b[1] * (b[3] * b[8] - b[5] * b[6]) +
            b[2] * (b[3] * b[7] - b[4] * b[6]);
        const float idet = 1.0f / det;
        inv[0] = (b[4] * b[8] - b[5] * b[7]) * idet;
        inv[1] = (b[2] * b[7] - b[1] * b[8]) * idet;
        inv[2] = (b[1] * b[5] - b[2] * b[4]) * idet;
        inv[3] = (b[5] * b[6] - b[3] * b[8]) * idet;
        inv[4] = (b[0] * b[8] - b[2] * b[6]) * idet;
        inv[5] = (b[2] * b[3] - b[0] * b[5]) * idet;
        inv[6] = (b[3] * b[7] - b[4] * b[6]) * idet;
        inv[7] = (b[1] * b[6] - b[0] * b[7]) * idet;
        inv[8] = (b[0] * b[4] - b[1] * b[3]) * idet;
    }

    __syncthreads();   // staging complete

    const float PI_OVER_RC = 3.14159265358979323846f / RCUT;

    // Accumulators: [0..8] radial (S_n = acc[n]); [9..17] V_n; [18..35] M_n.
    float acc[36];
#pragma unroll
    for (int k = 0; k < 36; k++) acc[k] = 0.0f;

    if (valid) {
        const float rix = sR[3 * i + 0];
        const float riy = sR[3 * i + 1];
        const float riz = sR[3 * i + 2];

        for (int j = lane + 32 * sub; j < N; j += 64) {
            if (j == i) continue;
            float cx = rix - sR[3 * j + 0];
            float cy = riy - sR[3 * j + 1];
            float cz = riz - sR[3 * j + 2];
            float dx, dy, dz;
            if (diag) {
                dx = cx - b[0] * rintf(inv[0] * cx);
                dy = cy - b[4] * rintf(inv[4] * cy);
                dz = cz - b[8] * rintf(inv[8] * cz);
            } else {
                float f0 = rintf(inv[0] * cx + inv[1] * cy + inv[2] * cz);
                float f1 = rintf(inv[3] * cx + inv[4] * cy + inv[5] * cz);
                float f2 = rintf(inv[6] * cx + inv[7] * cy + inv[8] * cz);
                dx = cx - (b[0] * f0 + b[1] * f1 + b[2] * f2);
                dy = cy - (b[3] * f0 + b[4] * f1 + b[5] * f2);
                dz = cz - (b[6] * f0 + b[7] * f1 + b[8] * f2);
            }
            float r2 = dx * dx + dy * dy + dz * dz;
            float invr = rsqrtf(r2);
            float r = r2 * invr;
            if (r >= RCUT) continue;   // fc exactly 0 there

            float fc = 0.5f * __cosf(r * PI_OVER_RC) + 0.5f;

            // Radial moments fc * r^k, k = 0..8 (log-depth powers)
            float rr2 = r * r;
            float rr3 = rr2 * r;
            float rr4 = rr2 * rr2;
            float fcr4 = fc * rr4;
            acc[0] += fc;
            acc[1] += fc * r;
            acc[2] += fc * rr2;
            acc[3] += fc * rr3;
            acc[4] += fcr4;
            acc[5] += fcr4 * r;
            acc[6] += fcr4 * rr2;
            acc[7] += fcr4 * rr3;
            acc[8] += fcr4 * rr4;

            // Angular weights: wv_n = fc r^(n-1), wm_n = fc r^(n-2)
            float wv0 = fc * invr;
            float wv2 = fc * r;
            float wm0 = wv0 * invr;
            float xx = dx * dx, xy = dx * dy, xz = dx * dz;
            float yy = dy * dy, yz = dy * dz, zz = dz * dz;

            acc[9]  += wv0 * dx;  acc[10] += wv0 * dy;  acc[11] += wv0 * dz;
            acc[12] += fc  * dx;  acc[13] += fc  * dy;  acc[14] += fc  * dz;
            acc[15] += wv2 * dx;  acc[16] += wv2 * dy;  acc[17] += wv2 * dz;

            acc[18] += wm0 * xx;  acc[19] += wm0 * xy;  acc[20] += wm0 * xz;
            acc[21] += wm0 * yy;  acc[22] += wm0 * yz;  acc[23] += wm0 * zz;
            acc[24] += wv0 * xx;  acc[25] += wv0 * xy;  acc[26] += wv0 * xz;
            acc[27] += wv0 * yy;  acc[28] += wv0 * yz;  acc[29] += wv0 * zz;
            acc[30] += fc  * xx;  acc[31] += fc  * xy;  acc[32] += fc  * xz;
            acc[33] += fc  * yy;  acc[34] += fc  * yz;  acc[35] += fc  * zz;
        }

        // ---- Split-butterfly warp reduction: 36 -> 18 -> 9 -> 5 -> 3 -> 2 ----
        float v18[18];
        {
            const bool up = (lane & 16) != 0;
#pragma unroll
            for (int k = 0; k < 18; k++) {
                float lo = acc[k]      + __shfl_xor_sync(0xffffffffu, acc[k], 16);
                float hi = acc[18 + k] + __shfl_xor_sync(0xffffffffu, acc[18 + k], 16);
                v18[k] = up ? hi : lo;
            }
        }
        float v9[9];
        {
            const bool up = (lane & 8) != 0;
#pragma unroll
            for (int k = 0; k < 9; k++) {
                float lo = v18[k]     + __shfl_xor_sync(0xffffffffu, v18[k], 8);
                float hi = v18[9 + k] + __shfl_xor_sync(0xffffffffu, v18[9 + k], 8);
                v9[k] = up ? hi : lo;
            }
        }
        float v5[5];
        {
            const bool up = (lane & 4) != 0;
#pragma unroll
            for (int k = 0; k < 5; k++) {
                float lo = v9[k] + __shfl_xor_sync(0xffffffffu, v9[k], 4);
                float hi = 0.0f;
                if (k < 4)
                    hi = v9[5 + k] + __shfl_xor_sync(0xffffffffu, v9[5 + k], 4);
                v5[k] = up ? hi : lo;   // upper group: only 4 valid
            }
        }
        float v3[3];
        {
            const bool up = (lane & 2) != 0;
#pragma unroll
            for (int k = 0; k < 3; k++) {
                float lo = v5[k] + __shfl_xor_sync(0xffffffffu, v5[k], 2);
                float hi = 0.0f;
                if (k < 2)
                    hi = v5[3 + k] + __shfl_xor_sync(0xffffffffu, v5[3 + k], 2);
                v3[k] = up ? hi : lo;
            }
        }
        float v2[2];
        {
            const bool up = (lane & 1) != 0;
#pragma unroll
            for (int k = 0; k < 2; k++) {
                float lo = v3[k] + __shfl_xor_sync(0xffffffffu, v3[k], 1);
                float hi = 0.0f;
                if (k < 1)
                    hi = v3[2] + __shfl_xor_sync(0xffffffffu, v3[2], 1);
                v2[k] = up ? hi : lo;
            }
        }

        // Deterministic scatter into this warp's private smem slot.
        const int b4 = (lane >> 4) & 1, b3 = (lane >> 3) & 1;
        const int b2 = (lane >> 2) & 1, b1 = (lane >> 1) & 1, b0 = lane & 1;
        const int gsize = b2 ? 4 : 5;
        const int off0  = b1 * 3 + b0 * 2;
        const int base  = b4 * 18 + b3 * 9 + b2 * 5;
        if (off0 < gsize)                sred[a][sub][base + off0]     = v2[0];
        if (b0 == 0 && off0 + 1 < gsize) sred[a][sub][base + off0 + 1] = v2[1];
    }

    // Barrier scoped to this atom's warp pair only (ids 1 and 2, 64 threads).
    asm volatile("bar.sync %0, %1;" :: "r"(a + 1), "r"(64) : "memory");

    // Epilogue: 18 lanes of the sub==0 warp combine the two halves + write.
    if (valid && sub == 0 && lane < 18) {
        const float* p0 = sred[a][0];
        const float* p1 = sred[a][1];
#define TOT(k) (p0[k] + p1[k])

        float val;
        if (lane < 9) {
            val = TOT(lane);
        } else {
            int idx = lane - 9;
            int n = idx / 3;
            int l = idx - 3 * n;
            float s = TOT(n);
            if (l == 0) {
                val = s * s;
            } else if (l == 1) {
                float vx = TOT(9 + 3 * n), vy = TOT(10 + 3 * n), vz = TOT(11 + 3 * n);
                val = vx * vx + vy * vy + vz * vz;
            } else {
                float m0 = TOT(18 + 6 * n), m1 = TOT(19 + 6 * n), m2 = TOT(20 + 6 * n);
                float m3 = TOT(21 + 6 * n), m4 = TOT(22 + 6 * n), m5 = TOT(23 + 6 * n);
                float frob = m0 * m0 + m3 * m3 + m5 * m5 +
                             2.0f * (m1 * m1 + m2 * m2 + m4 * m4);
                val = 0.5f * (3.0f * frob - s * s);
            }
        }
        out[(size_t)i * 18 + lane] = val;
#undef TOT
    }
}

extern "C" void kernel_launch(void* const* d_in, const int* in_sizes, int n_in,
                              void* d_out, int out_size) {
    const float* R   = (const float*)d_in[0];   // [N,3] fp32
    // d_in[1] = Z (int32), unused by the reference math
    const float* box = (const float*)d_in[2];   // [3,3] fp32
    float* out = (float*)d_out;                 // [N,18] fp32
    const int N = in_sizes[0] / 3;
    const int blocks = (N + 1) / 2;             // 2 atoms per block
    desc_kernel<<<blocks, BLOCK>>>(R, box, out, N);
}

// round 8
// speedup vs baseline: 1.3413x; 1.0288x over previous
#include <cuda_runtime.h>
#include <cuda_bf16.h>
#include <math.h>

// DescriptorBuilder: periodic minimum-image descriptors (O(N^2) factorized).
// Radial:  q_r[i,k] = sum_j fc(r_ij) * r_ij^k, k=0..8
// Angular: q_ang[i,n,0] = S_n^2, S_n = sum_j fc r^n
//          q_ang[i,n,1] = |V_n|^2, V_n = sum_j fc r^(n-1) dr
//          q_ang[i,n,2] = 0.5*(3*||M_n||_F^2 - S_n^2), M_n = sum_j fc r^(n-2) dr(x)dr
//
// Best-measured R3 structure: 128 threads/block, 2 warps per atom (split
// j-range), 2 atoms per block, 96 blocks = one wave; full warp butterfly;
// sub==1 warp publishes to smem; block barrier; 18-lane epilogue.
// Pre-barrier improvements only: float4 staging of raw coords, diagonal-box
// fast path, N==192 specialization with batched LDS (3 unrolled iterations).

#define BLOCK 128
#define MAXN 512
#define RCUT 6.0f

__global__ void __launch_bounds__(BLOCK)
desc_kernel(const float* __restrict__ R,
            const float* __restrict__ box,
            float* __restrict__ out, int N)
{
    __shared__ float sR[MAXN * 3];    // flat raw Cartesian coords
    __shared__ float sred[2][36];     // partial sums published by sub==1 warps

    const int t    = threadIdx.x;
    const int lane = t & 31;
    const int warp = t >> 5;        // 0..3
    const int a    = warp >> 1;     // atom slot (0/1)
    const int sub  = warp & 1;      // j-range half
    const int i    = blockIdx.x * 2 + a;
    const bool valid = (i < N);

    // ---- Vectorized staging: 3N floats via float4 ----
    {
        const int nflt = 3 * N;
        const int nvec = nflt >> 2;
        const float4* R4 = reinterpret_cast<const float4*>(R);
        float4* s4 = reinterpret_cast<float4*>(sR);
        for (int v = t; v < nvec; v += BLOCK) s4[v] = __ldg(R4 + v);
        for (int v = (nvec << 2) + t; v < nflt; v += BLOCK) sR[v] = __ldg(R + v);
    }

    // Box in registers; diagonal fast path avoids the 3x3 inverse.
    float b[9];
#pragma unroll
    for (int k = 0; k < 9; k++) b[k] = __ldg(box + k);

    const bool diag = (b[1] == 0.f && b[2] == 0.f && b[3] == 0.f &&
                       b[5] == 0.f && b[6] == 0.f && b[7] == 0.f);

    float inv[9];
    if (diag) {
        inv[0] = 1.0f / b[0];
        inv[4] = 1.0f / b[4];
        inv[8] = 1.0f / b[8];
    } else {
        const float det =
            b[0] * (b[4] * b[8] - b[5] * b[7]) -
            b[1] * (b[3] * b[8] - b[5] * b[6]) +
            b[2] * (b[3] * b[7] - b[4] * b[6]);
        const float idet = 1.0f / det;
        inv[0] = (b[4] * b[8] - b[5] * b[7]) * idet;
        inv[1] = (b[2] * b[7] - b[1] * b[8]) * idet;
        inv[2] = (b[1] * b[5] - b[2] * b[4]) * idet;
        inv[3] = (b[5] * b[6] - b[3] * b[8]) * idet;
        inv[4] = (b[0] * b[8] - b[2] * b[6]) * idet;
        inv[5] = (b[2] * b[3] - b[0] * b[5]) * idet;
        inv[6] = (b[3] * b[7] - b[4] * b[6]) * idet;
        inv[7] = (b[1] * b[6] - b[0] * b[7]) * idet;
        inv[8] = (b[0] * b[4] - b[1] * b[3]) * idet;
    }

    __syncthreads();   // staging complete

    const float PI_OVER_RC = 3.14159265358979323846f / RCUT;

    // Accumulators: [0..8] radial (S_n = acc[n]); [9..17] V_n; [18..35] M_n.
    float acc[36];
#pragma unroll
    for (int k = 0; k < 36; k++) acc[k] = 0.0f;

    if (valid) {
        const float rix = sR[3 * i + 0];
        const float riy = sR[3 * i + 1];
        const float riz = sR[3 * i + 2];
        const int j0 = lane + 32 * sub;

        // One pair-interaction body (accumulates into acc[]).
        auto body = [&](float cx, float cy, float cz, bool skip) {
            float dx, dy, dz;
            if (diag) {
                dx = cx - b[0] * rintf(inv[0] * cx);
                dy = cy - b[4] * rintf(inv[4] * cy);
                dz = cz - b[8] * rintf(inv[8] * cz);
            } else {
                float f0 = rintf(inv[0] * cx + inv[1] * cy + inv[2] * cz);
                float f1 = rintf(inv[3] * cx + inv[4] * cy + inv[5] * cz);
                float f2 = rintf(inv[6] * cx + inv[7] * cy + inv[8] * cz);
                dx = cx - (b[0] * f0 + b[1] * f1 + b[2] * f2);
                dy = cy - (b[3] * f0 + b[4] * f1 + b[5] * f2);
                dz = cz - (b[6] * f0 + b[7] * f1 + b[8] * f2);
            }
            float r2 = dx * dx + dy * dy + dz * dz;
            float invr = rsqrtf(r2);
            float r = r2 * invr;
            if (skip || r >= RCUT) return;   // fc exactly 0 at/beyond cutoff

            float fc = 0.5f * __cosf(r * PI_OVER_RC) + 0.5f;

            float rr2 = r * r;
            float rr3 = rr2 * r;
            float rr4 = rr2 * rr2;
            float fcr4 = fc * rr4;
            acc[0] += fc;
            acc[1] += fc * r;
            acc[2] += fc * rr2;
            acc[3] += fc * rr3;
            acc[4] += fcr4;
            acc[5] += fcr4 * r;
            acc[6] += fcr4 * rr2;
            acc[7] += fcr4 * rr3;
            acc[8] += fcr4 * rr4;

            float wv0 = fc * invr;
            float wv2 = fc * r;
            float wm0 = wv0 * invr;
            float xx = dx * dx, xy = dx * dy, xz = dx * dz;
            float yy = dy * dy, yz = dy * dz, zz = dz * dz;

            acc[9]  += wv0 * dx;  acc[10] += wv0 * dy;  acc[11] += wv0 * dz;
            acc[12] += fc  * dx;  acc[13] += fc  * dy;  acc[14] += fc  * dz;
            acc[15] += wv2 * dx;  acc[16] += wv2 * dy;  acc[17] += wv2 * dz;

            acc[18] += wm0 * xx;  acc[19] += wm0 * xy;  acc[20] += wm0 * xz;
            acc[21] += wm0 * yy;  acc[22] += wm0 * yz;  acc[23] += wm0 * zz;
            acc[24] += wv0 * xx;  acc[25] += wv0 * xy;  acc[26] += wv0 * xz;
            acc[27] += wv0 * yy;  acc[28] += wv0 * yz;  acc[29] += wv0 * zz;
            acc[30] += fc  * xx;  acc[31] += fc  * xy;  acc[32] += fc  * xz;
            acc[33] += fc  * yy;  acc[34] += fc  * yz;  acc[35] += fc  * zz;
        };

        if (N == 192) {
            // Exactly 3 iterations per lane: batch all 9 LDS up front so the
            // shared-memory latency is exposed once, not three times.
            const int ja = j0, jb = j0 + 64, jc = j0 + 128;
            float ax = sR[3 * ja], ay = sR[3 * ja + 1], az = sR[3 * ja + 2];
            float bx = sR[3 * jb], by = sR[3 * jb + 1], bz = sR[3 * jb + 2];
            float cx_ = sR[3 * jc], cy_ = sR[3 * jc + 1], cz_ = sR[3 * jc + 2];
            body(rix - ax,  riy - ay,  riz - az,  ja == i);
            body(rix - bx,  riy - by,  riz - bz,  jb == i);
            body(rix - cx_, riy - cy_, riz - cz_, jc == i);
        } else {
            for (int j = j0; j < N; j += 64) {
                body(rix - sR[3 * j], riy - sR[3 * j + 1], riz - sR[3 * j + 2],
                     j == i);
            }
        }

        // Full warp butterfly: afterwards EVERY lane holds all 36 sums.
#pragma unroll
        for (int k = 0; k < 36; k++) {
            float v = acc[k];
#pragma unroll
            for (int o = 16; o > 0; o >>= 1) v += __shfl_xor_sync(0xffffffffu, v, o);
            acc[k] = v;
        }
    }

    // Cross-warp combine: sub==1 warp publishes its 36 sums.
    if (sub == 1) {
        if (lane < 36) sred[a][lane] = acc[lane];
        if (lane < 4)  sred[a][32 + lane] = acc[32 + lane];
    }
    __syncthreads();

    // Epilogue: 18 lanes of the sub==0 warp combine + write.
    if (valid && sub == 0 && lane < 18) {
#pragma unroll
        for (int k = 0; k < 36; k++) acc[k] += sred[a][k];   // broadcast LDS

        float val;
        if (lane < 9) {
            val = acc[lane];
        } else {
            int idx = lane - 9;
            int n = idx / 3;
            int l = idx - 3 * n;
            float s = acc[n];
            if (l == 0) {
                val = s * s;
            } else if (l == 1) {
                float vx = acc[9 + 3 * n], vy = acc[10 + 3 * n], vz = acc[11 + 3 * n];
                val = vx * vx + vy * vy + vz * vz;
            } else {
                float m0 = acc[18 + 6 * n], m1 = acc[19 + 6 * n], m2 = acc[20 + 6 * n];
                float m3 = acc[21 + 6 * n], m4 = acc[22 + 6 * n], m5 = acc[23 + 6 * n];
                float frob = m0 * m0 + m3 * m3 + m5 * m5 +
                             2.0f * (m1 * m1 + m2 * m2 + m4 * m4);
                val = 0.5f * (3.0f * frob - s * s);
            }
        }
        out[(size_t)i * 18 + lane] = val;
    }
}

extern "C" void kernel_launch(void* const* d_in, const int* in_sizes, int n_in,
                              void* d_out, int out_size) {
    const float* R   = (const float*)d_in[0];   // [N,3] fp32
    // d_in[1] = Z (int32), unused by the reference math
    const float* box = (const float*)d_in[2];   // [3,3] fp32
    float* out = (float*)d_out;                 // [N,18] fp32
    const int N = in_sizes[0] / 3;
    const int blocks = (N + 1) / 2;             // 2 atoms per block
    desc_kernel<<<blocks, BLOCK>>>(R, box, out, N);
}